// round 1
// baseline (speedup 1.0000x reference)
#include <cuda_runtime.h>

// EMEncoder_21483426414987 — masked per-label means + overall masked mean.
// Shapes: tarsent_state [8,512,512] f32, tar_func [8,512] i32,
//         refsent_state [8,32,256,512] f32, ref_func [8,32,256] i32.
// Output: flat f32 concat of
//   tar_aug[8,5,512], tar_aug_mask[8,5], ref_aug[8,32,5,512], ref_aug_mask[8,32,5],
//   tarpaper[8,512], tar_mask2[8], refpaper[8,32,512], ref_mask2[8,32]
// Total = 812592 floats. Masks written as 1.0/0.0.

#define H    512
#define HQ   128   // H / 4 (float4 per row)
#define NLAB 5

// Flat float offsets of the 8 output regions
#define OFF_TAR_AUG   0
#define OFF_TAR_AMSK  20480
#define OFF_REF_AUG   20520
#define OFF_REF_AMSK  675880
#define OFF_TAR_PAP   677160
#define OFF_TAR_PMSK  681256
#define OFF_REF_PAP   681264
#define OFF_REF_PMSK  812336

__device__ __forceinline__ void f4add(float4& a, const float4& v) {
    a.x += v.x; a.y += v.y; a.z += v.z; a.w += v.w;
}

__global__ __launch_bounds__(256, 4) void em_reduce_kernel(
    const float* __restrict__ tar_state, const int* __restrict__ tar_func,
    const float* __restrict__ ref_state, const int* __restrict__ ref_func,
    float* __restrict__ out)
{
    __shared__ int    sfunc[512];
    __shared__ float4 spart[6][HQ];

    const int bid = blockIdx.x;
    const float4* state;
    const int*    func;
    int S;
    long aug_off, pap_off;
    int  amsk_off, pmsk_off;

    if (bid < 8) {
        const int b = bid;
        S        = 512;
        state    = (const float4*)(tar_state + (size_t)b * 512 * H);
        func     = tar_func + b * 512;
        aug_off  = OFF_TAR_AUG + (long)b * NLAB * H;
        amsk_off = OFF_TAR_AMSK + b * NLAB;
        pap_off  = OFF_TAR_PAP + (long)b * H;
        pmsk_off = OFF_TAR_PMSK + b;
    } else {
        const int idx = bid - 8;           // idx = b*32 + d, 0..255
        S        = 256;
        state    = (const float4*)(ref_state + (size_t)idx * 256 * H);
        func     = ref_func + idx * 256;
        aug_off  = OFF_REF_AUG + (long)idx * NLAB * H;
        amsk_off = OFF_REF_AMSK + idx * NLAB;
        pap_off  = OFF_REF_PAP + (long)idx * H;
        pmsk_off = OFF_REF_PMSK + idx;
    }

    const int tid = threadIdx.x;
    const int sub = tid >> 7;      // sentence sub-group 0/1
    const int hq  = tid & 127;     // float4 column owned by this thread

    // stage func labels into smem once
    for (int s = tid; s < S; s += 256) sfunc[s] = func[s];
    __syncthreads();

    float4 a1 = make_float4(0.f,0.f,0.f,0.f);
    float4 a2 = a1, a3 = a1, a4 = a1, a5 = a1, at = a1;

    // Main streaming loop: each thread strides by 2 sentences.
    // Labels are block-uniform per sentence -> no divergence.
    #pragma unroll 8
    for (int s = sub; s < S; s += 2) {
        float4 v = __ldg(&state[(size_t)s * HQ + hq]);
        int f = sfunc[s];
        if      (f == 1) f4add(a1, v);
        else if (f == 2) f4add(a2, v);
        else if (f == 3) f4add(a3, v);
        else if (f == 4) f4add(a4, v);
        else if (f == 5) f4add(a5, v);
        if (f != 0) f4add(at, v);
    }

    // Combine the two sentence sub-groups through smem
    if (sub == 1) {
        spart[0][hq] = a1; spart[1][hq] = a2; spart[2][hq] = a3;
        spart[3][hq] = a4; spart[4][hq] = a5; spart[5][hq] = at;
    }
    __syncthreads();

    if (sub == 0) {
        f4add(a1, spart[0][hq]); f4add(a2, spart[1][hq]); f4add(a3, spart[2][hq]);
        f4add(a4, spart[3][hq]); f4add(a5, spart[4][hq]); f4add(at, spart[5][hq]);

        // counts (identical across threads; recomputed from smem — cheap)
        int c1 = 0, c2 = 0, c3 = 0, c4 = 0, c5 = 0, ct = 0;
        for (int s = 0; s < S; s++) {
            int f = sfunc[s];
            c1 += (f == 1); c2 += (f == 2); c3 += (f == 3);
            c4 += (f == 4); c5 += (f == 5); ct += (f != 0);
        }

        float4* out4 = (float4*)out;
        const long aug4 = aug_off >> 2;
        const long pap4 = pap_off >> 2;

        float4 z = make_float4(0.f,0.f,0.f,0.f);
        #define WRITE_LBL(l, acc, cnt)                                        \
        {                                                                     \
            float4 r = z;                                                     \
            if (cnt > 0) {                                                    \
                float inv = 1.0f / (float)cnt;                                \
                r = make_float4(acc.x*inv, acc.y*inv, acc.z*inv, acc.w*inv);  \
            }                                                                 \
            out4[aug4 + (long)(l) * HQ + hq] = r;                             \
        }
        WRITE_LBL(0, a1, c1)
        WRITE_LBL(1, a2, c2)
        WRITE_LBL(2, a3, c3)
        WRITE_LBL(3, a4, c4)
        WRITE_LBL(4, a5, c5)
        #undef WRITE_LBL

        {
            float4 r = z;
            if (ct > 0) {
                float inv = 1.0f / (float)ct;
                r = make_float4(at.x*inv, at.y*inv, at.z*inv, at.w*inv);
            }
            out4[pap4 + hq] = r;
        }

        if (hq == 0) {
            out[amsk_off + 0] = (c1 > 0) ? 1.0f : 0.0f;
            out[amsk_off + 1] = (c2 > 0) ? 1.0f : 0.0f;
            out[amsk_off + 2] = (c3 > 0) ? 1.0f : 0.0f;
            out[amsk_off + 3] = (c4 > 0) ? 1.0f : 0.0f;
            out[amsk_off + 4] = (c5 > 0) ? 1.0f : 0.0f;
            out[pmsk_off]     = (ct > 0) ? 1.0f : 0.0f;
        }
    }
}

extern "C" void kernel_launch(void* const* d_in, const int* in_sizes, int n_in,
                              void* d_out, int out_size) {
    const float* tar_state = (const float*)d_in[0];
    const int*   tar_func  = (const int*)d_in[1];
    const float* ref_state = (const float*)d_in[2];
    const int*   ref_func  = (const int*)d_in[3];
    float* out = (float*)d_out;

    // 8 tar blocks + 256 ref blocks
    em_reduce_kernel<<<264, 256>>>(tar_state, tar_func, ref_state, ref_func, out);
}

// round 2
// speedup vs baseline: 3.6800x; 3.6800x over previous
#include <cuda_runtime.h>

// EMEncoder_21483426414987 — masked per-label means + overall masked mean.
// tarsent_state [8,512,512] f32, tar_func [8,512] i32,
// refsent_state [8,32,256,512] f32, ref_func [8,32,256] i32.
// Output flat f32: tar_aug[8,5,512], tar_aug_mask[8,5], ref_aug[8,32,5,512],
// ref_aug_mask[8,32,5], tarpaper[8,512], tar_mask2[8], refpaper[8,32,512],
// ref_mask2[8,32]. Total 812592 floats. Masks as 1.0/0.0.
//
// R2: split H into 4 chunks of 32 float4 cols per tile -> 1056 independent
// blocks (no cross-block combine needed), cooperative count computation.

#define H      512
#define HQ     128      // H/4 float4 per row
#define NLAB   5
#define CHUNKS 4
#define CW     32       // float4 columns per chunk (HQ / CHUNKS)
#define NSUB   8        // sentence subgroups per block (256 threads / 32 cols)

#define OFF_TAR_AUG   0
#define OFF_TAR_AMSK  20480
#define OFF_REF_AUG   20520
#define OFF_REF_AMSK  675880
#define OFF_TAR_PAP   677160
#define OFF_TAR_PMSK  681256
#define OFF_REF_PAP   681264
#define OFF_REF_PMSK  812336

__device__ __forceinline__ void f4add(float4& a, const float4& v) {
    a.x += v.x; a.y += v.y; a.z += v.z; a.w += v.w;
}

__global__ __launch_bounds__(256, 4) void em_reduce_kernel(
    const float* __restrict__ tar_state, const int* __restrict__ tar_func,
    const float* __restrict__ ref_state, const int* __restrict__ ref_func,
    float* __restrict__ out)
{
    __shared__ int    sfunc[512];
    __shared__ int    scnt[6];
    __shared__ float4 spart[NSUB - 1][6][CW];

    const int bid = blockIdx.x;
    const float4* state;
    const int*    func;
    int S, chunk;
    long aug_off, pap_off;
    int  amsk_off, pmsk_off;

    if (bid < 8 * CHUNKS) {
        const int b = bid >> 2;
        chunk    = bid & 3;
        S        = 512;
        state    = (const float4*)(tar_state + (size_t)b * 512 * H);
        func     = tar_func + b * 512;
        aug_off  = OFF_TAR_AUG + (long)b * NLAB * H;
        amsk_off = OFF_TAR_AMSK + b * NLAB;
        pap_off  = OFF_TAR_PAP + (long)b * H;
        pmsk_off = OFF_TAR_PMSK + b;
    } else {
        const int r   = bid - 8 * CHUNKS;
        const int idx = r >> 2;            // b*32 + d, 0..255
        chunk    = r & 3;
        S        = 256;
        state    = (const float4*)(ref_state + (size_t)idx * 256 * H);
        func     = ref_func + idx * 256;
        aug_off  = OFF_REF_AUG + (long)idx * NLAB * H;
        amsk_off = OFF_REF_AMSK + idx * NLAB;
        pap_off  = OFF_REF_PAP + (long)idx * H;
        pmsk_off = OFF_REF_PMSK + idx;
    }

    const int tid = threadIdx.x;
    const int sub = tid >> 5;          // sentence subgroup 0..7 (= warp id)
    const int col = tid & 31;          // column within chunk
    const int hq  = chunk * CW + col;  // global float4 column

    if (tid < 6) scnt[tid] = 0;
    __syncthreads();

    // Stage func labels into smem + cooperative label counts
    {
        int l1 = 0, l2 = 0, l3 = 0, l4 = 0, l5 = 0, lt = 0;
        for (int s = tid; s < S; s += 256) {
            int f = func[s];
            sfunc[s] = f;
            l1 += (f == 1); l2 += (f == 2); l3 += (f == 3);
            l4 += (f == 4); l5 += (f == 5); lt += (f != 0);
        }
        if (l1) atomicAdd(&scnt[0], l1);
        if (l2) atomicAdd(&scnt[1], l2);
        if (l3) atomicAdd(&scnt[2], l3);
        if (l4) atomicAdd(&scnt[3], l4);
        if (l5) atomicAdd(&scnt[4], l5);
        if (lt) atomicAdd(&scnt[5], lt);
    }
    __syncthreads();

    float4 a1 = make_float4(0.f,0.f,0.f,0.f);
    float4 a2 = a1, a3 = a1, a4 = a1, a5 = a1, at = a1;

    // Main streaming loop: subgroup sub handles sentences sub, sub+8, ...
    // Labels block-uniform per sentence -> zero divergence within warps.
    #pragma unroll 8
    for (int s = sub; s < S; s += NSUB) {
        float4 v = __ldg(&state[(size_t)s * HQ + hq]);
        int f = sfunc[s];
        if      (f == 1) f4add(a1, v);
        else if (f == 2) f4add(a2, v);
        else if (f == 3) f4add(a3, v);
        else if (f == 4) f4add(a4, v);
        else if (f == 5) f4add(a5, v);
        if (f != 0) f4add(at, v);
    }

    // Combine 8 subgroups through smem: subs 1..7 publish, sub 0 reduces.
    if (sub > 0) {
        const int p = sub - 1;
        spart[p][0][col] = a1; spart[p][1][col] = a2; spart[p][2][col] = a3;
        spart[p][3][col] = a4; spart[p][4][col] = a5; spart[p][5][col] = at;
    }
    __syncthreads();

    if (sub == 0) {
        #pragma unroll
        for (int p = 0; p < NSUB - 1; p++) {
            f4add(a1, spart[p][0][col]); f4add(a2, spart[p][1][col]);
            f4add(a3, spart[p][2][col]); f4add(a4, spart[p][3][col]);
            f4add(a5, spart[p][4][col]); f4add(at, spart[p][5][col]);
        }

        const int c1 = scnt[0], c2 = scnt[1], c3 = scnt[2];
        const int c4 = scnt[3], c5 = scnt[4], ct = scnt[5];

        float4* out4 = (float4*)out;
        const long aug4 = aug_off >> 2;
        const long pap4 = pap_off >> 2;
        const float4 z = make_float4(0.f,0.f,0.f,0.f);

        #define WRITE_LBL(l, acc, cnt)                                        \
        {                                                                     \
            float4 r = z;                                                     \
            if (cnt > 0) {                                                    \
                float inv = 1.0f / (float)cnt;                                \
                r = make_float4(acc.x*inv, acc.y*inv, acc.z*inv, acc.w*inv);  \
            }                                                                 \
            out4[aug4 + (long)(l) * HQ + hq] = r;                             \
        }
        WRITE_LBL(0, a1, c1)
        WRITE_LBL(1, a2, c2)
        WRITE_LBL(2, a3, c3)
        WRITE_LBL(3, a4, c4)
        WRITE_LBL(4, a5, c5)
        #undef WRITE_LBL

        {
            float4 r = z;
            if (ct > 0) {
                float inv = 1.0f / (float)ct;
                r = make_float4(at.x*inv, at.y*inv, at.z*inv, at.w*inv);
            }
            out4[pap4 + hq] = r;
        }

        if (chunk == 0 && col == 0) {
            out[amsk_off + 0] = (c1 > 0) ? 1.0f : 0.0f;
            out[amsk_off + 1] = (c2 > 0) ? 1.0f : 0.0f;
            out[amsk_off + 2] = (c3 > 0) ? 1.0f : 0.0f;
            out[amsk_off + 3] = (c4 > 0) ? 1.0f : 0.0f;
            out[amsk_off + 4] = (c5 > 0) ? 1.0f : 0.0f;
            out[pmsk_off]     = (ct > 0) ? 1.0f : 0.0f;
        }
    }
}

extern "C" void kernel_launch(void* const* d_in, const int* in_sizes, int n_in,
                              void* d_out, int out_size) {
    const float* tar_state = (const float*)d_in[0];
    const int*   tar_func  = (const int*)d_in[1];
    const float* ref_state = (const float*)d_in[2];
    const int*   ref_func  = (const int*)d_in[3];
    float* out = (float*)d_out;

    // (8 tar + 256 ref) tiles x 4 H-chunks
    em_reduce_kernel<<<(8 + 256) * CHUNKS, 256>>>(tar_state, tar_func,
                                                  ref_state, ref_func, out);
}

// round 3
// speedup vs baseline: 3.7096x; 1.0080x over previous
#include <cuda_runtime.h>

// EMEncoder_21483426414987 — masked per-label means + overall masked mean.
// tarsent_state [8,512,512] f32, tar_func [8,512] i32,
// refsent_state [8,32,256,512] f32, ref_func [8,32,256] i32.
// Output flat f32: tar_aug[8,5,512], tar_aug_mask[8,5], ref_aug[8,32,5,512],
// ref_aug_mask[8,32,5], tarpaper[8,512], tar_mask2[8], refpaper[8,32,512],
// ref_mask2[8,32]. Total 812592 floats. Masks as 1.0/0.0.
//
// R3: paper-mean = sum of label sums (f!=0 <=> f in 1..5), so drop the 6th
// accumulator; smaller smem lets 8 blocks/SM reside -> single wave, ~100% occ.

#define H      512
#define HQ     128      // H/4 float4 per row
#define NLAB   5
#define CHUNKS 4
#define CW     32       // float4 columns per chunk (HQ / CHUNKS)
#define NSUB   8        // sentence subgroups per block (256 threads / 32 cols)

#define OFF_TAR_AUG   0
#define OFF_TAR_AMSK  20480
#define OFF_REF_AUG   20520
#define OFF_REF_AMSK  675880
#define OFF_TAR_PAP   677160
#define OFF_TAR_PMSK  681256
#define OFF_REF_PAP   681264
#define OFF_REF_PMSK  812336

__device__ __forceinline__ void f4add(float4& a, const float4& v) {
    a.x += v.x; a.y += v.y; a.z += v.z; a.w += v.w;
}

__global__ __launch_bounds__(256) void em_reduce_kernel(
    const float* __restrict__ tar_state, const int* __restrict__ tar_func,
    const float* __restrict__ ref_state, const int* __restrict__ ref_func,
    float* __restrict__ out)
{
    __shared__ int    sfunc[512];
    __shared__ int    scnt[NLAB];
    __shared__ float4 spart[NSUB - 1][NLAB][CW];

    const int bid = blockIdx.x;
    const float4* state;
    const int*    func;
    int S, chunk;
    long aug_off, pap_off;
    int  amsk_off, pmsk_off;

    if (bid < 8 * CHUNKS) {
        const int b = bid >> 2;
        chunk    = bid & 3;
        S        = 512;
        state    = (const float4*)(tar_state + (size_t)b * 512 * H);
        func     = tar_func + b * 512;
        aug_off  = OFF_TAR_AUG + (long)b * NLAB * H;
        amsk_off = OFF_TAR_AMSK + b * NLAB;
        pap_off  = OFF_TAR_PAP + (long)b * H;
        pmsk_off = OFF_TAR_PMSK + b;
    } else {
        const int r   = bid - 8 * CHUNKS;
        const int idx = r >> 2;            // b*32 + d, 0..255
        chunk    = r & 3;
        S        = 256;
        state    = (const float4*)(ref_state + (size_t)idx * 256 * H);
        func     = ref_func + idx * 256;
        aug_off  = OFF_REF_AUG + (long)idx * NLAB * H;
        amsk_off = OFF_REF_AMSK + idx * NLAB;
        pap_off  = OFF_REF_PAP + (long)idx * H;
        pmsk_off = OFF_REF_PMSK + idx;
    }

    const int tid = threadIdx.x;
    const int sub = tid >> 5;          // sentence subgroup 0..7 (= warp id)
    const int col = tid & 31;          // column within chunk
    const int hq  = chunk * CW + col;  // global float4 column

    if (tid < NLAB) scnt[tid] = 0;
    __syncthreads();

    // Stage func labels into smem + cooperative label counts
    {
        int l1 = 0, l2 = 0, l3 = 0, l4 = 0, l5 = 0;
        for (int s = tid; s < S; s += 256) {
            int f = func[s];
            sfunc[s] = f;
            l1 += (f == 1); l2 += (f == 2); l3 += (f == 3);
            l4 += (f == 4); l5 += (f == 5);
        }
        if (l1) atomicAdd(&scnt[0], l1);
        if (l2) atomicAdd(&scnt[1], l2);
        if (l3) atomicAdd(&scnt[2], l3);
        if (l4) atomicAdd(&scnt[3], l4);
        if (l5) atomicAdd(&scnt[4], l5);
    }
    __syncthreads();

    float4 a1 = make_float4(0.f,0.f,0.f,0.f);
    float4 a2 = a1, a3 = a1, a4 = a1, a5 = a1;

    // Main streaming loop: subgroup sub handles sentences sub, sub+8, ...
    // Labels block-uniform per sentence -> zero divergence within warps.
    #pragma unroll 8
    for (int s = sub; s < S; s += NSUB) {
        float4 v = __ldg(&state[(size_t)s * HQ + hq]);
        int f = sfunc[s];
        if      (f == 1) f4add(a1, v);
        else if (f == 2) f4add(a2, v);
        else if (f == 3) f4add(a3, v);
        else if (f == 4) f4add(a4, v);
        else if (f == 5) f4add(a5, v);
    }

    // Combine 8 subgroups through smem: subs 1..7 publish, sub 0 reduces.
    if (sub > 0) {
        const int p = sub - 1;
        spart[p][0][col] = a1; spart[p][1][col] = a2; spart[p][2][col] = a3;
        spart[p][3][col] = a4; spart[p][4][col] = a5;
    }
    __syncthreads();

    if (sub == 0) {
        #pragma unroll
        for (int p = 0; p < NSUB - 1; p++) {
            f4add(a1, spart[p][0][col]); f4add(a2, spart[p][1][col]);
            f4add(a3, spart[p][2][col]); f4add(a4, spart[p][3][col]);
            f4add(a5, spart[p][4][col]);
        }

        const int c1 = scnt[0], c2 = scnt[1], c3 = scnt[2];
        const int c4 = scnt[3], c5 = scnt[4];
        const int ct = c1 + c2 + c3 + c4 + c5;

        // paper sum = sum over all non-pad = sum of the 5 label sums
        float4 at;
        at.x = a1.x + a2.x + a3.x + a4.x + a5.x;
        at.y = a1.y + a2.y + a3.y + a4.y + a5.y;
        at.z = a1.z + a2.z + a3.z + a4.z + a5.z;
        at.w = a1.w + a2.w + a3.w + a4.w + a5.w;

        float4* out4 = (float4*)out;
        const long aug4 = aug_off >> 2;
        const long pap4 = pap_off >> 2;
        const float4 z = make_float4(0.f,0.f,0.f,0.f);

        #define WRITE_LBL(l, acc, cnt)                                        \
        {                                                                     \
            float4 r = z;                                                     \
            if (cnt > 0) {                                                    \
                float inv = 1.0f / (float)cnt;                                \
                r = make_float4(acc.x*inv, acc.y*inv, acc.z*inv, acc.w*inv);  \
            }                                                                 \
            out4[aug4 + (long)(l) * HQ + hq] = r;                             \
        }
        WRITE_LBL(0, a1, c1)
        WRITE_LBL(1, a2, c2)
        WRITE_LBL(2, a3, c3)
        WRITE_LBL(3, a4, c4)
        WRITE_LBL(4, a5, c5)
        #undef WRITE_LBL

        {
            float4 r = z;
            if (ct > 0) {
                float inv = 1.0f / (float)ct;
                r = make_float4(at.x*inv, at.y*inv, at.z*inv, at.w*inv);
            }
            out4[pap4 + hq] = r;
        }

        if (chunk == 0 && col == 0) {
            out[amsk_off + 0] = (c1 > 0) ? 1.0f : 0.0f;
            out[amsk_off + 1] = (c2 > 0) ? 1.0f : 0.0f;
            out[amsk_off + 2] = (c3 > 0) ? 1.0f : 0.0f;
            out[amsk_off + 3] = (c4 > 0) ? 1.0f : 0.0f;
            out[amsk_off + 4] = (c5 > 0) ? 1.0f : 0.0f;
            out[pmsk_off]     = (ct > 0) ? 1.0f : 0.0f;
        }
    }
}

extern "C" void kernel_launch(void* const* d_in, const int* in_sizes, int n_in,
                              void* d_out, int out_size) {
    const float* tar_state = (const float*)d_in[0];
    const int*   tar_func  = (const int*)d_in[1];
    const float* ref_state = (const float*)d_in[2];
    const int*   ref_func  = (const int*)d_in[3];
    float* out = (float*)d_out;

    // (8 tar + 256 ref) tiles x 4 H-chunks
    em_reduce_kernel<<<(8 + 256) * CHUNKS, 256>>>(tar_state, tar_func,
                                                  ref_state, ref_func, out);
}

// round 4
// speedup vs baseline: 5.5664x; 1.5005x over previous
#include <cuda_runtime.h>

// EMEncoder_21483426414987 — masked per-label means + overall masked mean.
// tarsent_state [8,512,512] f32, tar_func [8,512] i32,
// refsent_state [8,32,256,512] f32, ref_func [8,32,256] i32.
// Output flat f32: tar_aug[8,5,512], tar_aug_mask[8,5], ref_aug[8,32,5,512],
// ref_aug_mask[8,32,5], tarpaper[8,512], tar_mask2[8], refpaper[8,32,512],
// ref_mask2[8,32]. Total 812592 floats. Masks as 1.0/0.0.
//
// R4: smem accumulators (regs<=32 -> 8 blocks/SM, single wave), skip f==0
// rows (block-uniform branch, ~17% less DRAM traffic), equalized blocks:
// tar = 8 tiles x 8 chunks of 16 cols, ref = 256 tiles x 4 chunks of 32 cols;
// every block = 32 iterations, 128KB read.

#define H    512
#define HQ   128    // H/4 float4 per row
#define NLAB 5

#define OFF_TAR_AUG   0
#define OFF_TAR_AMSK  20480
#define OFF_REF_AUG   20520
#define OFF_REF_AMSK  675880
#define OFF_TAR_PAP   677160
#define OFF_TAR_PMSK  681256
#define OFF_REF_PAP   681264
#define OFF_REF_PMSK  812336

__device__ __forceinline__ void f4add(float4& a, const float4& v) {
    a.x += v.x; a.y += v.y; a.z += v.z; a.w += v.w;
}

__global__ __launch_bounds__(256, 8) void em_reduce_kernel(
    const float* __restrict__ tar_state, const int* __restrict__ tar_func,
    const float* __restrict__ ref_state, const int* __restrict__ ref_func,
    float* __restrict__ out)
{
    __shared__ float4 sacc[NLAB * 256];   // [label][tid] partial sums
    __shared__ int    sfunc[512];
    __shared__ int    scnt[NLAB];

    const int bid = blockIdx.x;
    const float4* state;
    const int*    func;
    int S, chunk, wsh;        // wsh: log2(subgroup width)
    long aug_off, pap_off;
    int  amsk_off, pmsk_off;

    if (bid < 64) {                       // tar: 8 tiles x 8 chunks (CW=16)
        const int b = bid >> 3;
        chunk    = bid & 7;
        wsh      = 4;                     // width 16, 16 subgroups
        S        = 512;
        state    = (const float4*)(tar_state + (size_t)b * 512 * H);
        func     = tar_func + b * 512;
        aug_off  = OFF_TAR_AUG + (long)b * NLAB * H;
        amsk_off = OFF_TAR_AMSK + b * NLAB;
        pap_off  = OFF_TAR_PAP + (long)b * H;
        pmsk_off = OFF_TAR_PMSK + b;
    } else {                              // ref: 256 tiles x 4 chunks (CW=32)
        const int r   = bid - 64;
        const int idx = r >> 2;           // b*32 + d
        chunk    = r & 3;
        wsh      = 5;                     // width 32, 8 subgroups
        S        = 256;
        state    = (const float4*)(ref_state + (size_t)idx * 256 * H);
        func     = ref_func + idx * 256;
        aug_off  = OFF_REF_AUG + (long)idx * NLAB * H;
        amsk_off = OFF_REF_AMSK + idx * NLAB;
        pap_off  = OFF_REF_PAP + (long)idx * H;
        pmsk_off = OFF_REF_PMSK + idx;
    }

    const int tid  = threadIdx.x;
    const int Wc   = 1 << wsh;            // subgroup width (cols)
    const int NS   = 256 >> wsh;          // #subgroups
    const int colw = tid & (Wc - 1);
    const int sub  = tid >> wsh;
    const int hq   = chunk * Wc + colw;   // global float4 column

    // zero smem accumulators
    const float4 z = make_float4(0.f, 0.f, 0.f, 0.f);
    #pragma unroll
    for (int i = 0; i < NLAB; i++) sacc[i * 256 + tid] = z;
    if (tid < NLAB) scnt[tid] = 0;

    // stage func + cooperative counts
    {
        int l1 = 0, l2 = 0, l3 = 0, l4 = 0, l5 = 0;
        for (int s = tid; s < S; s += 256) {
            int f = func[s];
            sfunc[s] = f;
            l1 += (f == 1); l2 += (f == 2); l3 += (f == 3);
            l4 += (f == 4); l5 += (f == 5);
        }
        __syncthreads();                  // scnt zeroed & sacc zeroed
        if (l1) atomicAdd(&scnt[0], l1);
        if (l2) atomicAdd(&scnt[1], l2);
        if (l3) atomicAdd(&scnt[2], l3);
        if (l4) atomicAdd(&scnt[3], l4);
        if (l5) atomicAdd(&scnt[4], l5);
    }
    __syncthreads();

    // Main loop: exactly 32 iterations per block (S/NS == 32 both paths).
    // Label uniform per subgroup -> branch is divergence-free; f==0 rows are
    // never loaded from DRAM.
    #pragma unroll 8
    for (int i = 0; i < 32; i++) {
        const int s = sub + (i << (8 - wsh));   // sub + i*NS
        const int f = sfunc[s];
        if (f != 0) {
            float4 v = __ldg(&state[(size_t)s * HQ + hq]);
            float4 o = sacc[(f - 1) * 256 + tid];
            f4add(o, v);
            sacc[(f - 1) * 256 + tid] = o;
        }
    }
    __syncthreads();

    // Epilogue: warp l (0..4) reduces label l across subgroups; warp 5 does
    // the paper mean; one thread writes masks.
    const int wid  = tid >> 5;
    const int lane = tid & 31;
    float4* out4 = (float4*)out;
    const long aug4 = aug_off >> 2;
    const long pap4 = pap_off >> 2;

    if (wid < NLAB) {
        if (lane < Wc) {
            float4 ssum = z;
            for (int p = 0; p < NS; p++)
                f4add(ssum, sacc[wid * 256 + p * Wc + lane]);
            const int cnt = scnt[wid];
            float4 r = z;
            if (cnt > 0) {
                float inv = 1.0f / (float)cnt;
                r = make_float4(ssum.x*inv, ssum.y*inv, ssum.z*inv, ssum.w*inv);
            }
            out4[aug4 + (long)wid * HQ + chunk * Wc + lane] = r;
        }
    } else if (wid == 5) {
        if (lane < Wc) {
            float4 ssum = z;
            for (int l = 0; l < NLAB; l++)
                for (int p = 0; p < NS; p++)
                    f4add(ssum, sacc[l * 256 + p * Wc + lane]);
            const int ct = scnt[0] + scnt[1] + scnt[2] + scnt[3] + scnt[4];
            float4 r = z;
            if (ct > 0) {
                float inv = 1.0f / (float)ct;
                r = make_float4(ssum.x*inv, ssum.y*inv, ssum.z*inv, ssum.w*inv);
            }
            out4[pap4 + chunk * Wc + lane] = r;
        }
    } else if (wid == 6 && lane == 0 && chunk == 0) {
        const int c1 = scnt[0], c2 = scnt[1], c3 = scnt[2];
        const int c4 = scnt[3], c5 = scnt[4];
        out[amsk_off + 0] = (c1 > 0) ? 1.0f : 0.0f;
        out[amsk_off + 1] = (c2 > 0) ? 1.0f : 0.0f;
        out[amsk_off + 2] = (c3 > 0) ? 1.0f : 0.0f;
        out[amsk_off + 3] = (c4 > 0) ? 1.0f : 0.0f;
        out[amsk_off + 4] = (c5 > 0) ? 1.0f : 0.0f;
        out[pmsk_off] = ((c1 + c2 + c3 + c4 + c5) > 0) ? 1.0f : 0.0f;
    }
}

extern "C" void kernel_launch(void* const* d_in, const int* in_sizes, int n_in,
                              void* d_out, int out_size) {
    const float* tar_state = (const float*)d_in[0];
    const int*   tar_func  = (const int*)d_in[1];
    const float* ref_state = (const float*)d_in[2];
    const int*   ref_func  = (const int*)d_in[3];
    float* out = (float*)d_out;

    // 8 tar tiles x 8 chunks + 256 ref tiles x 4 chunks = 1088 equal blocks
    em_reduce_kernel<<<64 + 1024, 256>>>(tar_state, tar_func,
                                         ref_state, ref_func, out);
}